// round 1
// baseline (speedup 1.0000x reference)
#include <cuda_runtime.h>
#include <math.h>

// Problem constants
#define BATCH 4
#define HW 16384          // 128*128
#define HH 128
#define WW 128
#define OFFC 18           // 2*K
#define KK 9
#define CMID 128
#define EPS 1e-5f

// -------- scratch (device globals; no allocation) --------
__device__ float g_off[BATCH * OFFC * HW];          // offset maps (4.7 MB)
__device__ float g_t1 [BATCH * CMID * HW];          // stage1 activations (33.5 MB)
__device__ float g_t2 [BATCH * CMID * HW];          // stage2 pre-BN (33.5 MB)
__device__ float g_stats[2 * CMID];                 // per-channel scale, shift
__device__ float g_wt1[576  * 128];                 // w1 transposed [ck][o]
__device__ float g_wt2[1152 * 128];                 // w2 transposed [ck][o]

// -------- weight transpose: wt[ck*128 + o] = w[o*CK + ck] --------
__global__ void transpose_w_kernel(const float* __restrict__ w, float* __restrict__ wt, int CK) {
    int i = blockIdx.x * blockDim.x + threadIdx.x;
    if (i < CK * 128) {
        int o  = i / CK;
        int ck = i - o * CK;
        wt[ck * 128 + o] = w[i];
    }
}

// -------- 3x3 offset conv (pad 1). One thread = 4 consecutive w pixels. --------
template<int C>
__global__ void conv3x3_off_kernel(const float* __restrict__ x,
                                   const float* __restrict__ w,
                                   const float* __restrict__ bias,
                                   float* __restrict__ out)
{
    __shared__ float ws[C * 9];
    const int bo = blockIdx.y;         // b*18 + oc
    const int b  = bo / OFFC;
    const int oc = bo - b * OFFC;
    for (int i = threadIdx.x; i < C * 9; i += blockDim.x)
        ws[i] = w[oc * C * 9 + i];
    __syncthreads();

    const int quad = blockIdx.x * blockDim.x + threadIdx.x;   // 0..4095
    if (quad >= 4096) return;
    const int h  = quad >> 5;            // 32 quads per row
    const int w0 = (quad & 31) << 2;

    const float* xb = x + (size_t)b * C * HW;
    float acc0 = bias[oc], acc1 = acc0, acc2 = acc0, acc3 = acc0;

    for (int c = 0; c < C; c++) {
        const float* xc = xb + c * HW;
        float r[3][6];
        #pragma unroll
        for (int dy = 0; dy < 3; dy++) {
            int y = h - 1 + dy;
            bool yv = (y >= 0) && (y < HH);
            #pragma unroll
            for (int dx = 0; dx < 6; dx++) {
                int xx = w0 - 1 + dx;
                r[dy][dx] = (yv && xx >= 0 && xx < WW) ? xc[y * WW + xx] : 0.f;
            }
        }
        const float* wc = ws + c * 9;
        #pragma unroll
        for (int dy = 0; dy < 3; dy++) {
            #pragma unroll
            for (int kx = 0; kx < 3; kx++) {
                float wv = wc[dy * 3 + kx];
                acc0 += wv * r[dy][kx + 0];
                acc1 += wv * r[dy][kx + 1];
                acc2 += wv * r[dy][kx + 2];
                acc3 += wv * r[dy][kx + 3];
            }
        }
    }
    float4 v = make_float4(acc0, acc1, acc2, acc3);
    *reinterpret_cast<float4*>(&out[((size_t)bo) * HW + h * WW + w0]) = v;
}

// -------- fused deformable conv as implicit GEMM --------
// Block: all 128 output channels x 64 pixels. Thread micro-tile: 8 o x 4 px.
// S (bilinear samples) built in SMEM per 8-ck chunk; each sample computed once.
template<int C>
__global__ void __launch_bounds__(256)
deform_kernel(const float* __restrict__ x,
              const float* __restrict__ offset,
              const float* __restrict__ wt,     // [CK][128]
              const float* __restrict__ bias,
              float* __restrict__ out)
{
    constexpr int CK = C * 9;
    const int b     = blockIdx.y;
    const int pbase = blockIdx.x * 64;
    const int t  = threadIdx.x;
    const int pg = t & 15;
    const int og = t >> 4;
    const int o0 = og * 8;
    const int p0 = pg * 4;

    __shared__ float Ws[8][128];
    __shared__ float Ss[8][64];

    float acc[8][4];
    #pragma unroll
    for (int i = 0; i < 8; i++)
        #pragma unroll
        for (int j = 0; j < 4; j++) acc[i][j] = 0.f;

    const float* xb   = x + (size_t)b * C * HW;
    const float* offb = offset + (size_t)b * OFFC * HW;

    for (int ck0 = 0; ck0 < CK; ck0 += 8) {
        __syncthreads();
        // weights: 8 x 128, coalesced float4
        {
            int idx = t * 4;
            int kc = idx >> 7, oo = idx & 127;
            *reinterpret_cast<float4*>(&Ws[kc][oo]) =
                *reinterpret_cast<const float4*>(&wt[(ck0 + kc) * 128 + oo]);
        }
        // samples: 8 ck x 64 px, 2 per thread
        #pragma unroll
        for (int r = 0; r < 2; r++) {
            int idx = t + r * 256;
            int kc = idx >> 6, pl = idx & 63;
            int ck = ck0 + kc;
            int c = ck / 9;
            int k = ck - c * 9;
            int pixel = pbase + pl;
            int h = pixel >> 7, w = pixel & 127;
            float offy = offb[(2 * k) * HW + pixel];
            float offx = offb[(2 * k + 1) * HW + pixel];
            float py = (float)(h - 1 + k / 3) + offy;
            float px = (float)(w - 1 + (k - (k / 3) * 3)) + offx;
            float fy = floorf(py), fx = floorf(px);
            int y0 = (int)fy, x0 = (int)fx;
            float wy1 = py - fy, wx1 = px - fx;
            float wy0 = 1.f - wy1, wx0 = 1.f - wx1;
            const float* xc = xb + c * HW;
            bool y0v = (y0 >= 0) && (y0 < HH);
            bool y1v = (y0 + 1 >= 0) && (y0 + 1 < HH);
            bool x0v = (x0 >= 0) && (x0 < WW);
            bool x1v = (x0 + 1 >= 0) && (x0 + 1 < WW);
            float v00 = (y0v && x0v) ? xc[(y0 << 7) + x0]           : 0.f;
            float v01 = (y0v && x1v) ? xc[(y0 << 7) + x0 + 1]       : 0.f;
            float v10 = (y1v && x0v) ? xc[((y0 + 1) << 7) + x0]     : 0.f;
            float v11 = (y1v && x1v) ? xc[((y0 + 1) << 7) + x0 + 1] : 0.f;
            Ss[kc][pl] = wy0 * (wx0 * v00 + wx1 * v01) + wy1 * (wx0 * v10 + wx1 * v11);
        }
        __syncthreads();
        #pragma unroll
        for (int kc = 0; kc < 8; kc++) {
            float sv[4], wv[8];
            *reinterpret_cast<float4*>(sv)     = *reinterpret_cast<const float4*>(&Ss[kc][p0]);
            *reinterpret_cast<float4*>(wv)     = *reinterpret_cast<const float4*>(&Ws[kc][o0]);
            *reinterpret_cast<float4*>(wv + 4) = *reinterpret_cast<const float4*>(&Ws[kc][o0 + 4]);
            #pragma unroll
            for (int i = 0; i < 8; i++)
                #pragma unroll
                for (int j = 0; j < 4; j++)
                    acc[i][j] += wv[i] * sv[j];
        }
    }

    float* ob = out + (size_t)b * 128 * HW + pbase;
    #pragma unroll
    for (int i = 0; i < 8; i++) {
        int o = o0 + i;
        float bo = bias[o];
        float4 v = make_float4(acc[i][0] + bo, acc[i][1] + bo,
                               acc[i][2] + bo, acc[i][3] + bo);
        *reinterpret_cast<float4*>(&ob[(size_t)o * HW + p0]) = v;
    }
}

// -------- BN stats: one block per channel -> scale/shift --------
__global__ void bn_stats_kernel(const float* __restrict__ t,
                                const float* __restrict__ gamma,
                                const float* __restrict__ beta,
                                float* __restrict__ stats)
{
    const int c = blockIdx.x;
    float s = 0.f, s2 = 0.f;
    for (int b = 0; b < BATCH; b++) {
        const float* p = t + ((size_t)b * CMID + c) * HW;
        for (int i = threadIdx.x; i < HW; i += blockDim.x) {
            float v = p[i];
            s += v; s2 += v * v;
        }
    }
    __shared__ float sh[512], sh2[512];
    sh[threadIdx.x] = s; sh2[threadIdx.x] = s2;
    __syncthreads();
    for (int st = 256; st > 0; st >>= 1) {
        if (threadIdx.x < st) {
            sh[threadIdx.x]  += sh[threadIdx.x + st];
            sh2[threadIdx.x] += sh2[threadIdx.x + st];
        }
        __syncthreads();
    }
    if (threadIdx.x == 0) {
        const float n = (float)(BATCH * HW);
        float mean = sh[0] / n;
        float var  = sh2[0] / n - mean * mean;
        float inv  = rsqrtf(var + EPS);
        float sc   = gamma[c] * inv;
        stats[c]        = sc;
        stats[CMID + c] = beta[c] - mean * sc;
    }
}

// -------- BN apply + ReLU (vectorized) --------
__global__ void bn_apply_kernel(const float* __restrict__ in,
                                const float* __restrict__ stats,
                                float* __restrict__ out)
{
    const int total4 = BATCH * CMID * HW / 4;
    int i = blockIdx.x * blockDim.x + threadIdx.x;
    if (i >= total4) return;
    int e = i * 4;
    int c = (e >> 14) & 127;             // HW = 16384 per (b,c) slab
    float sc = stats[c], sh = stats[CMID + c];
    float4 v = reinterpret_cast<const float4*>(in)[i];
    v.x = fmaxf(v.x * sc + sh, 0.f);
    v.y = fmaxf(v.y * sc + sh, 0.f);
    v.z = fmaxf(v.z * sc + sh, 0.f);
    v.w = fmaxf(v.w * sc + sh, 0.f);
    reinterpret_cast<float4*>(out)[i] = v;
}

extern "C" void kernel_launch(void* const* d_in, const int* in_sizes, int n_in,
                              void* d_out, int out_size)
{
    const float* x      = (const float*)d_in[0];
    const float* w_off1 = (const float*)d_in[1];
    const float* b_off1 = (const float*)d_in[2];
    const float* w1     = (const float*)d_in[3];
    const float* b1     = (const float*)d_in[4];
    const float* g1     = (const float*)d_in[5];
    const float* be1    = (const float*)d_in[6];
    const float* w_off2 = (const float*)d_in[7];
    const float* b_off2 = (const float*)d_in[8];
    const float* w2     = (const float*)d_in[9];
    const float* b2     = (const float*)d_in[10];
    const float* g2     = (const float*)d_in[11];
    const float* be2    = (const float*)d_in[12];
    float* out = (float*)d_out;

    float *off, *t1, *t2, *stats, *wt1, *wt2;
    cudaGetSymbolAddress((void**)&off,   g_off);
    cudaGetSymbolAddress((void**)&t1,    g_t1);
    cudaGetSymbolAddress((void**)&t2,    g_t2);
    cudaGetSymbolAddress((void**)&stats, g_stats);
    cudaGetSymbolAddress((void**)&wt1,   g_wt1);
    cudaGetSymbolAddress((void**)&wt2,   g_wt2);

    // weight transposes
    transpose_w_kernel<<<(576 * 128 + 255) / 256, 256>>>(w1, wt1, 576);
    transpose_w_kernel<<<(1152 * 128 + 255) / 256, 256>>>(w2, wt2, 1152);

    // stage 1
    conv3x3_off_kernel<64><<<dim3(16, BATCH * OFFC), 256>>>(x, w_off1, b_off1, off);
    deform_kernel<64><<<dim3(HW / 64, BATCH), 256>>>(x, off, wt1, b1, t1);
    bn_stats_kernel<<<CMID, 512>>>(t1, g1, be1, stats);
    bn_apply_kernel<<<(BATCH * CMID * HW / 4 + 255) / 256, 256>>>(t1, stats, t1);

    // stage 2
    conv3x3_off_kernel<128><<<dim3(16, BATCH * OFFC), 256>>>(t1, w_off2, b_off2, off);
    deform_kernel<128><<<dim3(HW / 64, BATCH), 256>>>(t1, off, wt2, b2, t2);
    bn_stats_kernel<<<CMID, 512>>>(t2, g2, be2, stats);
    bn_apply_kernel<<<(BATCH * CMID * HW / 4 + 255) / 256, 256>>>(t2, stats, out);
}